// round 2
// baseline (speedup 1.0000x reference)
#include <cuda_runtime.h>
#include <cstddef>

// ---------------------------------------------------------------------------
// Decoder_73495480369571: 6-layer dense 3D transposed-conv decoder, fp32.
//
// jax.lax.conv_transpose semantics (transpose_kernel=False, SAME, k=3):
//   stride 1: ordinary SAME cross-correlation, pad 1.
//   stride 2: lhs_dilation=2, pad (2,1). Per dimension:
//       out[2m]   = in[m-1]*w[0] + in[m]*w[2]   (in[m-1] dropped at m==0)
//       out[2m+1] = in[m]*w[1]
//
// Weights are DHWIO: w[kz][ky][kx][ci][co], co contiguous.
// Activations NCDHW (N=1): a[ci][z][y][x], x contiguous.
// ---------------------------------------------------------------------------

// Scratch (allocation-free rule: __device__ globals).
__device__ float g_h1[512 * 512];        // 512 x 8^3
__device__ float g_h2[256 * 512];        // 256 x 8^3
__device__ float g_h3[128 * 4096];       // 128 x 16^3
__device__ float g_h4[64 * 4096];        // 64 x 16^3
__device__ float g_h5[32 * 32768];       // 32 x 32^3
__device__ float g_p1[4 * 512 * 512];    // L1 split-K partials
__device__ float g_p2[4 * 256 * 512];    // L2 split-K partials
__device__ float g_p3[2 * 128 * 4096];   // L3 split-K partials
__device__ float g_p4[4 * 64 * 4096];    // L4 split-K partials

// ---------------------------------------------------------------------------
// Stride-2 transposed conv. Each thread: one co, one (z,y) of the 2*DXIN
// output cube, full output x-row (2*DXIN accumulators) in registers.
// blockIdx.z = split-K chunk (writes its own partial slab).
// ---------------------------------------------------------------------------
template <int DXIN, bool RELU>
__global__ void ct_s2(const float* __restrict__ in, const float* __restrict__ w,
                      float* __restrict__ out, int Ci, int Co, int ciPerSplit)
{
    constexpr int DO = 2 * DXIN;
    const int co = blockIdx.y * blockDim.x + threadIdx.x;
    const int z  = blockIdx.x / DO;
    const int y  = blockIdx.x % DO;
    const int ci0 = blockIdx.z * ciPerSplit;
    const int ci1 = ci0 + ciPerSplit;
    out += (size_t)blockIdx.z * Co * (DO * DO * DO);

    float acc[DO];
#pragma unroll
    for (int i = 0; i < DO; i++) acc[i] = 0.f;

    // Valid (k, input-index) taps for z and y: (z+k) even, 0 <= (z+k-2)/2 < DXIN
    int zk[2], zi[2], nz = 0;
#pragma unroll
    for (int k = 0; k < 3; k++) {
        if (((z + k) & 1) == 0) {
            int t = (z + k - 2) / 2;
            if (t >= 0 && t < DXIN) { zk[nz] = k; zi[nz] = t; nz++; }
        }
    }
    int yk[2], yi[2], ny = 0;
#pragma unroll
    for (int k = 0; k < 3; k++) {
        if (((y + k) & 1) == 0) {
            int t = (y + k - 2) / 2;
            if (t >= 0 && t < DXIN) { yk[ny] = k; yi[ny] = t; ny++; }
        }
    }

    const int CC = Ci * Co;
    for (int ci = ci0; ci < ci1; ci++) {
        const float* inc = in + (size_t)ci * (DXIN * DXIN * DXIN);
        for (int a = 0; a < nz; a++) {
            for (int b = 0; b < ny; b++) {
                const float* row = inc + (zi[a] * DXIN + yi[b]) * DXIN;
                float rin[DXIN];
#pragma unroll
                for (int x = 0; x < DXIN; x++) rin[x] = __ldg(row + x);

                const float* wp = w + (size_t)((zk[a] * 3 + yk[b]) * 3) * CC
                                    + (size_t)ci * Co + co;
                const float w0 = __ldg(wp);
                const float w1 = __ldg(wp + CC);
                const float w2 = __ldg(wp + 2 * CC);
#pragma unroll
                for (int m = 1; m < DXIN; m++) acc[2 * m]     += rin[m - 1] * w0;
#pragma unroll
                for (int m = 0; m < DXIN; m++) acc[2 * m + 1] += rin[m] * w1;
#pragma unroll
                for (int m = 0; m < DXIN; m++) acc[2 * m]     += rin[m] * w2;
            }
        }
    }

    float* op = out + (((size_t)co * DO + z) * DO + y) * DO;
#pragma unroll
    for (int xo = 0; xo < DO; xo++) {
        float v = acc[xo];
        if (RELU) v = fmaxf(v, 0.f);
        op[xo] = v;
    }
}

// ---------------------------------------------------------------------------
// Stride-1 SAME conv (3^3, pad 1). Same thread mapping: co x (z,y), full x-row.
// ---------------------------------------------------------------------------
template <int DX, bool RELU>
__global__ void ct_s1(const float* __restrict__ in, const float* __restrict__ w,
                      float* __restrict__ out, int Ci, int Co, int ciPerSplit)
{
    const int co = blockIdx.y * blockDim.x + threadIdx.x;
    const int z  = blockIdx.x / DX;
    const int y  = blockIdx.x % DX;
    const int ci0 = blockIdx.z * ciPerSplit;
    const int ci1 = ci0 + ciPerSplit;
    out += (size_t)blockIdx.z * Co * (DX * DX * DX);

    float acc[DX];
#pragma unroll
    for (int i = 0; i < DX; i++) acc[i] = 0.f;

    const int CC = Ci * Co;
    for (int ci = ci0; ci < ci1; ci++) {
        const float* inc = in + (size_t)ci * (DX * DX * DX);
#pragma unroll
        for (int kz = 0; kz < 3; kz++) {
            const int zi = z + kz - 1;
            if (zi < 0 || zi >= DX) continue;
#pragma unroll
            for (int ky = 0; ky < 3; ky++) {
                const int yi = y + ky - 1;
                if (yi < 0 || yi >= DX) continue;
                const float* row = inc + (zi * DX + yi) * DX;
                float rin[DX];
#pragma unroll
                for (int x = 0; x < DX; x++) rin[x] = __ldg(row + x);

                const float* wp = w + (size_t)((kz * 3 + ky) * 3) * CC
                                    + (size_t)ci * Co + co;
                const float w0 = __ldg(wp);
                const float w1 = __ldg(wp + CC);
                const float w2 = __ldg(wp + 2 * CC);
#pragma unroll
                for (int x = 1; x < DX; x++)     acc[x] += rin[x - 1] * w0;
#pragma unroll
                for (int x = 0; x < DX; x++)     acc[x] += rin[x] * w1;
#pragma unroll
                for (int x = 0; x < DX - 1; x++) acc[x] += rin[x + 1] * w2;
            }
        }
    }

    float* op = out + (((size_t)co * DX + z) * DX + y) * DX;
#pragma unroll
    for (int x = 0; x < DX; x++) {
        float v = acc[x];
        if (RELU) v = fmaxf(v, 0.f);
        op[x] = v;
    }
}

// ---------------------------------------------------------------------------
// Final layer: Ci=32 -> Co=1, D=32, stride 1, no ReLU. One thread per voxel,
// weights (27*32 floats) staged in smem. Lane-consecutive x -> coalesced loads.
// ---------------------------------------------------------------------------
__global__ void ct_final(const float* __restrict__ in, const float* __restrict__ w,
                         float* __restrict__ out)
{
    constexpr int Ci = 32, D = 32;
    __shared__ float ws[27 * Ci];
    for (int i = threadIdx.x; i < 27 * Ci; i += blockDim.x) ws[i] = w[i];
    __syncthreads();

    const int idx = blockIdx.x * blockDim.x + threadIdx.x;
    const int x = idx & 31;
    const int y = (idx >> 5) & 31;
    const int z = idx >> 10;

    float acc = 0.f;
#pragma unroll
    for (int kz = 0; kz < 3; kz++) {
        const int zi = z + kz - 1;
        if (zi < 0 || zi >= D) continue;
#pragma unroll
        for (int ky = 0; ky < 3; ky++) {
            const int yi = y + ky - 1;
            if (yi < 0 || yi >= D) continue;
#pragma unroll
            for (int kx = 0; kx < 3; kx++) {
                const int xi = x + kx - 1;
                if (xi < 0 || xi >= D) continue;
                const float* ip = in + (zi * D + yi) * D + xi;
                const float* wk = ws + ((kz * 3 + ky) * 3 + kx) * Ci;
#pragma unroll 4
                for (int ci = 0; ci < Ci; ci++)
                    acc += __ldg(ip + (size_t)ci * D * D * D) * wk[ci];
            }
        }
    }
    out[idx] = acc;
}

// Fixed-order split-K reduction + ReLU (bit-deterministic).
__global__ void reduce_relu(const float* __restrict__ part, float* __restrict__ out,
                            int n, int S)
{
    const int i = blockIdx.x * blockDim.x + threadIdx.x;
    if (i >= n) return;
    float v = 0.f;
    for (int s = 0; s < S; s++) v += part[(size_t)s * n + i];
    out[i] = fmaxf(v, 0.f);
}

// ---------------------------------------------------------------------------
extern "C" void kernel_launch(void* const* d_in, const int* in_sizes, int n_in,
                              void* d_out, int out_size)
{
    (void)in_sizes; (void)n_in; (void)out_size;
    const float* x  = (const float*)d_in[0];
    const float* w1 = (const float*)d_in[1];
    const float* w2 = (const float*)d_in[2];
    const float* w3 = (const float*)d_in[3];
    const float* w4 = (const float*)d_in[4];
    const float* w5 = (const float*)d_in[5];
    const float* w6 = (const float*)d_in[6];
    float* out = (float*)d_out;

    float *h1, *h2, *h3, *h4, *h5, *p1, *p2, *p3, *p4;
    cudaGetSymbolAddress((void**)&h1, g_h1);
    cudaGetSymbolAddress((void**)&h2, g_h2);
    cudaGetSymbolAddress((void**)&h3, g_h3);
    cudaGetSymbolAddress((void**)&h4, g_h4);
    cudaGetSymbolAddress((void**)&h5, g_h5);
    cudaGetSymbolAddress((void**)&p1, g_p1);
    cudaGetSymbolAddress((void**)&p2, g_p2);
    cudaGetSymbolAddress((void**)&p3, g_p3);
    cudaGetSymbolAddress((void**)&p4, g_p4);

    // L1: 1024 -> 512, 4^3 -> 8^3, stride 2, split-K 4
    ct_s2<4, false><<<dim3(64, 4, 4), 128>>>(x, w1, p1, 1024, 512, 256);
    reduce_relu<<<(512 * 512 + 255) / 256, 256>>>(p1, h1, 512 * 512, 4);

    // L2: 512 -> 256, 8^3, stride 1, split-K 4
    ct_s1<8, false><<<dim3(64, 2, 4), 128>>>(h1, w2, p2, 512, 256, 128);
    reduce_relu<<<(256 * 512 + 255) / 256, 256>>>(p2, h2, 256 * 512, 4);

    // L3: 256 -> 128, 8^3 -> 16^3, stride 2, split-K 2
    ct_s2<8, false><<<dim3(256, 1, 2), 128>>>(h2, w3, p3, 256, 128, 128);
    reduce_relu<<<(128 * 4096 + 255) / 256, 256>>>(p3, h3, 128 * 4096, 2);

    // L4: 128 -> 64, 16^3, stride 1, split-K 4
    ct_s1<16, false><<<dim3(256, 1, 4), 64>>>(h3, w4, p4, 128, 64, 32);
    reduce_relu<<<(64 * 4096 + 255) / 256, 256>>>(p4, h4, 64 * 4096, 4);

    // L5: 64 -> 32, 16^3 -> 32^3, stride 2, fused ReLU
    ct_s2<16, true><<<dim3(1024, 1, 1), 32>>>(h4, w5, h5, 64, 32, 64);

    // L6: 32 -> 1, 32^3, stride 1, no ReLU
    ct_final<<<256, 128>>>(h5, w6, out);
}

// round 3
// speedup vs baseline: 2.2684x; 2.2684x over previous
#include <cuda_runtime.h>
#include <cstddef>

// ---------------------------------------------------------------------------
// Decoder_73495480369571: 6-layer dense 3D transposed-conv decoder, fp32.
// conv_transpose (transpose_kernel=False, SAME, k=3):
//   stride 1: SAME cross-correlation pad 1.
//   stride 2: per dim: out[2m] = in[m-1]*w[0] + in[m]*w[2]; out[2m+1] = in[m]*w[1]
// Weights DHWIO: w[kz][ky][kx][ci][co] (co contiguous). Acts NCDHW (N=1).
// ---------------------------------------------------------------------------

// Scratch (__device__ globals; allocation-free rule).
__device__ float g_h1[512 * 512];
__device__ float g_h2[256 * 512];
__device__ float g_h3[128 * 4096];
__device__ float g_h4[64 * 4096];
__device__ float g_h5[32 * 32768];
__device__ float g_p1[8  * 512 * 512];    // L1 partials
__device__ float g_p2[16 * 256 * 512];    // L2 partials
__device__ float g_p3[8  * 128 * 4096];   // L3 partials
__device__ float g_p4[16 * 64 * 4096];    // L4 partials
__device__ float g_p5[4  * 32 * 32768];   // L5 partials

template <int VEC>
__device__ __forceinline__ void ldw(const float* __restrict__ p, float* v) {
    if constexpr (VEC == 2) {
        float2 t = __ldg((const float2*)p);
        v[0] = t.x; v[1] = t.y;
    } else {
        v[0] = __ldg(p);
    }
}

// ---------------------------------------------------------------------------
// Stride-2 transposed conv. Thread: VEC consecutive co, one (z,y), full output
// x-row (2*DXIN accs per co) in registers. blockIdx.z = split-K chunk.
// ---------------------------------------------------------------------------
template <int DXIN, int VEC>
__global__ void ct_s2(const float* __restrict__ in, const float* __restrict__ w,
                      float* __restrict__ out, int Ci, int Co, int ciChunk)
{
    constexpr int DO = 2 * DXIN;
    const int co = (blockIdx.y * blockDim.x + threadIdx.x) * VEC;
    const int z  = blockIdx.x / DO;
    const int y  = blockIdx.x % DO;
    const int ci0 = blockIdx.z * ciChunk;
    out += (size_t)blockIdx.z * Co * (DO * DO * DO);

    float acc[VEC][DO];
#pragma unroll
    for (int v = 0; v < VEC; v++)
#pragma unroll
        for (int i = 0; i < DO; i++) acc[v][i] = 0.f;

    int zk[2], zi[2], nz = 0;
#pragma unroll
    for (int k = 0; k < 3; k++)
        if (((z + k) & 1) == 0) {
            int t = (z + k - 2) / 2;
            if (t >= 0 && t < DXIN) { zk[nz] = k; zi[nz] = t; nz++; }
        }
    int yk[2], yi[2], ny = 0;
#pragma unroll
    for (int k = 0; k < 3; k++)
        if (((y + k) & 1) == 0) {
            int t = (y + k - 2) / 2;
            if (t >= 0 && t < DXIN) { yk[ny] = k; yi[ny] = t; ny++; }
        }

    const int CC = Ci * Co;
    for (int ci = ci0; ci < ci0 + ciChunk; ci++) {
        const float* inc = in + (size_t)ci * (DXIN * DXIN * DXIN);
        for (int a = 0; a < nz; a++) {
            for (int b = 0; b < ny; b++) {
                const float* row = inc + (zi[a] * DXIN + yi[b]) * DXIN;
                float rin[DXIN];
#pragma unroll
                for (int q = 0; q < DXIN / 4; q++) {
                    float4 t = __ldg((const float4*)row + q);
                    rin[4 * q + 0] = t.x; rin[4 * q + 1] = t.y;
                    rin[4 * q + 2] = t.z; rin[4 * q + 3] = t.w;
                }
                const float* wp = w + (size_t)((zk[a] * 3 + yk[b]) * 3) * CC
                                    + (size_t)ci * Co + co;
                float w0[VEC], w1[VEC], w2[VEC];
                ldw<VEC>(wp, w0); ldw<VEC>(wp + CC, w1); ldw<VEC>(wp + 2 * CC, w2);
#pragma unroll
                for (int v = 0; v < VEC; v++) {
#pragma unroll
                    for (int m = 1; m < DXIN; m++) acc[v][2 * m]     += rin[m - 1] * w0[v];
#pragma unroll
                    for (int m = 0; m < DXIN; m++) acc[v][2 * m + 1] += rin[m] * w1[v];
#pragma unroll
                    for (int m = 0; m < DXIN; m++) acc[v][2 * m]     += rin[m] * w2[v];
                }
            }
        }
    }

#pragma unroll
    for (int v = 0; v < VEC; v++) {
        float* op = out + (((size_t)(co + v) * DO + z) * DO + y) * DO;
#pragma unroll
        for (int xo = 0; xo < DO; xo++) op[xo] = acc[v][xo];
    }
}

// ---------------------------------------------------------------------------
// Stride-1 SAME conv (3^3, pad 1). Same mapping.
// ---------------------------------------------------------------------------
template <int DX, int VEC>
__global__ void ct_s1(const float* __restrict__ in, const float* __restrict__ w,
                      float* __restrict__ out, int Ci, int Co, int ciChunk)
{
    const int co = (blockIdx.y * blockDim.x + threadIdx.x) * VEC;
    const int z  = blockIdx.x / DX;
    const int y  = blockIdx.x % DX;
    const int ci0 = blockIdx.z * ciChunk;
    out += (size_t)blockIdx.z * Co * (DX * DX * DX);

    float acc[VEC][DX];
#pragma unroll
    for (int v = 0; v < VEC; v++)
#pragma unroll
        for (int i = 0; i < DX; i++) acc[v][i] = 0.f;

    const int CC = Ci * Co;
    for (int ci = ci0; ci < ci0 + ciChunk; ci++) {
        const float* inc = in + (size_t)ci * (DX * DX * DX);
#pragma unroll
        for (int kz = 0; kz < 3; kz++) {
            const int ziv = z + kz - 1;
            if (ziv < 0 || ziv >= DX) continue;
#pragma unroll
            for (int ky = 0; ky < 3; ky++) {
                const int yiv = y + ky - 1;
                if (yiv < 0 || yiv >= DX) continue;
                const float* row = inc + (ziv * DX + yiv) * DX;
                float rin[DX];
#pragma unroll
                for (int q = 0; q < DX / 4; q++) {
                    float4 t = __ldg((const float4*)row + q);
                    rin[4 * q + 0] = t.x; rin[4 * q + 1] = t.y;
                    rin[4 * q + 2] = t.z; rin[4 * q + 3] = t.w;
                }
                const float* wp = w + (size_t)((kz * 3 + ky) * 3) * CC
                                    + (size_t)ci * Co + co;
                float w0[VEC], w1[VEC], w2[VEC];
                ldw<VEC>(wp, w0); ldw<VEC>(wp + CC, w1); ldw<VEC>(wp + 2 * CC, w2);
#pragma unroll
                for (int v = 0; v < VEC; v++) {
#pragma unroll
                    for (int x = 1; x < DX; x++)     acc[v][x] += rin[x - 1] * w0[v];
#pragma unroll
                    for (int x = 0; x < DX; x++)     acc[v][x] += rin[x] * w1[v];
#pragma unroll
                    for (int x = 0; x < DX - 1; x++) acc[v][x] += rin[x + 1] * w2[v];
                }
            }
        }
    }

#pragma unroll
    for (int v = 0; v < VEC; v++) {
        float* op = out + (((size_t)(co + v) * DX + z) * DX + y) * DX;
#pragma unroll
        for (int x = 0; x < DX; x++) op[x] = acc[v][x];
    }
}

// ---------------------------------------------------------------------------
// Final layer: Ci=32 -> Co=1, D=32, stride 1, no ReLU.
// ---------------------------------------------------------------------------
__global__ void ct_final(const float* __restrict__ in, const float* __restrict__ w,
                         float* __restrict__ out)
{
    constexpr int Ci = 32, D = 32;
    __shared__ float ws[27 * Ci];
    for (int i = threadIdx.x; i < 27 * Ci; i += blockDim.x) ws[i] = w[i];
    __syncthreads();

    const int idx = blockIdx.x * blockDim.x + threadIdx.x;
    const int x = idx & 31;
    const int y = (idx >> 5) & 31;
    const int z = idx >> 10;

    float acc = 0.f;
#pragma unroll
    for (int kz = 0; kz < 3; kz++) {
        const int zi = z + kz - 1;
        if (zi < 0 || zi >= D) continue;
#pragma unroll
        for (int ky = 0; ky < 3; ky++) {
            const int yi = y + ky - 1;
            if (yi < 0 || yi >= D) continue;
#pragma unroll
            for (int kx = 0; kx < 3; kx++) {
                const int xi = x + kx - 1;
                if (xi < 0 || xi >= D) continue;
                const float* ip = in + (zi * D + yi) * D + xi;
                const float* wk = ws + ((kz * 3 + ky) * 3 + kx) * Ci;
#pragma unroll 8
                for (int ci = 0; ci < Ci; ci++)
                    acc += __ldg(ip + (size_t)ci * D * D * D) * wk[ci];
            }
        }
    }
    out[idx] = acc;
}

// Fixed-order split-K reduction + ReLU, float4-vectorized (deterministic).
__global__ void reduce_relu4(const float4* __restrict__ part, float4* __restrict__ out,
                             int n4, int S)
{
    const int i = blockIdx.x * blockDim.x + threadIdx.x;
    if (i >= n4) return;
    float4 v = make_float4(0.f, 0.f, 0.f, 0.f);
    for (int s = 0; s < S; s++) {
        float4 p = part[(size_t)s * n4 + i];
        v.x += p.x; v.y += p.y; v.z += p.z; v.w += p.w;
    }
    v.x = fmaxf(v.x, 0.f); v.y = fmaxf(v.y, 0.f);
    v.z = fmaxf(v.z, 0.f); v.w = fmaxf(v.w, 0.f);
    out[i] = v;
}

// ---------------------------------------------------------------------------
extern "C" void kernel_launch(void* const* d_in, const int* in_sizes, int n_in,
                              void* d_out, int out_size)
{
    (void)in_sizes; (void)n_in; (void)out_size;
    const float* x  = (const float*)d_in[0];
    const float* w1 = (const float*)d_in[1];
    const float* w2 = (const float*)d_in[2];
    const float* w3 = (const float*)d_in[3];
    const float* w4 = (const float*)d_in[4];
    const float* w5 = (const float*)d_in[5];
    const float* w6 = (const float*)d_in[6];
    float* out = (float*)d_out;

    float *h1, *h2, *h3, *h4, *h5, *p1, *p2, *p3, *p4, *p5;
    cudaGetSymbolAddress((void**)&h1, g_h1);
    cudaGetSymbolAddress((void**)&h2, g_h2);
    cudaGetSymbolAddress((void**)&h3, g_h3);
    cudaGetSymbolAddress((void**)&h4, g_h4);
    cudaGetSymbolAddress((void**)&h5, g_h5);
    cudaGetSymbolAddress((void**)&p1, g_p1);
    cudaGetSymbolAddress((void**)&p2, g_p2);
    cudaGetSymbolAddress((void**)&p3, g_p3);
    cudaGetSymbolAddress((void**)&p4, g_p4);
    cudaGetSymbolAddress((void**)&p5, g_p5);

    // L1: 1024->512, 4^3->8^3, s2. co-vec2 (256 groups), split 8, chunk 128.
    ct_s2<4, 2><<<dim3(64, 2, 8), 128>>>(x, w1, p1, 1024, 512, 128);
    reduce_relu4<<<(512 * 512 / 4 + 255) / 256, 256>>>((const float4*)p1, (float4*)h1,
                                                       512 * 512 / 4, 8);

    // L2: 512->256, 8^3, s1. co-vec2 (128 groups), split 16, chunk 32.
    ct_s1<8, 2><<<dim3(64, 1, 16), 128>>>(h1, w2, p2, 512, 256, 32);
    reduce_relu4<<<(256 * 512 / 4 + 255) / 256, 256>>>((const float4*)p2, (float4*)h2,
                                                       256 * 512 / 4, 16);

    // L3: 256->128, 8^3->16^3, s2. co-vec2 (64 groups), split 8, chunk 32.
    ct_s2<8, 2><<<dim3(256, 1, 8), 64>>>(h2, w3, p3, 256, 128, 32);
    reduce_relu4<<<(128 * 4096 / 4 + 255) / 256, 256>>>((const float4*)p3, (float4*)h3,
                                                        128 * 4096 / 4, 8);

    // L4: 128->64, 16^3, s1. co-vec2 (32 groups), split 16, chunk 8.
    ct_s1<16, 2><<<dim3(256, 1, 16), 32>>>(h3, w4, p4, 128, 64, 8);
    reduce_relu4<<<(64 * 4096 / 4 + 255) / 256, 256>>>((const float4*)p4, (float4*)h4,
                                                       64 * 4096 / 4, 16);

    // L5: 64->32, 16^3->32^3, s2. co-vec1 (32 lanes), split 4, chunk 16.
    ct_s2<16, 1><<<dim3(1024, 1, 4), 32>>>(h4, w5, p5, 64, 32, 16);
    reduce_relu4<<<(32 * 32768 / 4 + 255) / 256, 256>>>((const float4*)p5, (float4*)h5,
                                                        32 * 32768 / 4, 4);

    // L6: 32->1, 32^3, s1, no ReLU.
    ct_final<<<256, 128>>>(h5, w6, out);
}